// round 11
// baseline (speedup 1.0000x reference)
#include <cuda_runtime.h>
#include <math_constants.h>

// HPSS: S (2,2,1025,1024) fp32.
//   harm = median_31 along W (zero pad), perc = median_31 along H (zero pad)
//   mask_h = harm^2/(harm^2+perc^2), mask_p = perc^2/(harm^2+perc^2)
//   out[0:N) = S*mask_h ; out[N:2N) = S*mask_p
//
// R11: exact R9 algorithm (bitonic sort16 static-index network, shared sorted
// base + incremental sorted private set with depth-2 parallel insert, rank
// select) + __launch_bounds__(128, 7) to cap regs at 72 and fit a 7th CTA/SM
// (smem 32KB x 7 = 224KB <= 228KB). R7's spill was traced to Batcher sort's
// dynamic indexing, NOT the cap — this isolates the cap on the clean base.

#define IMG_H 1025
#define IMG_W 1024
#define N_IMG 4
#define HALO  15

#define TILE_W 64
#define TILE_H 32
#define PATCH_H (TILE_H + 2 * HALO)   // 62
#define PATCH_W (TILE_W + 2 * HALO)   // 94
#define PITCH   (PATCH_W + 1)         // 95 (odd -> conflict-free column access)
#define NTHREADS 128

// Bitonic sort, n=16: 80 CE, every array index a literal constant after
// unrolling (keeps v[] in registers — do not replace with Batcher).
__device__ __forceinline__ void sort16(float v[16]) {
#pragma unroll
    for (int k = 2; k <= 16; k <<= 1) {
#pragma unroll
        for (int j = k >> 1; j > 0; j >>= 1) {
#pragma unroll
            for (int i = 0; i < 16; i++) {
                int l = i ^ j;
                if (l > i) {
                    float a = v[i], b = v[l];
                    float mn = fminf(a, b);
                    float mx = fmaxf(a, b);
                    if ((i & k) == 0) { v[i] = mn; v[l] = mx; }
                    else              { v[i] = mx; v[l] = mn; }
                }
            }
        }
    }
}

// Rank-15 (0-indexed; 16th smallest) of sorted P[0..14] u sorted b[0..15].
__device__ __forceinline__ float sel16th(const float P[16], const float b[16]) {
    float c[16];
    c[0] = b[15];
#pragma unroll
    for (int j = 1; j <= 15; j++) c[j] = fmaxf(P[j - 1], b[15 - j]);
#pragma unroll
    for (int s = 8; s >= 1; s >>= 1)
#pragma unroll
        for (int j = 0; j < s; j++) c[j] = fminf(c[j], c[j + s]);
    return c[0];
}

// Replace value v (present in sorted P[0..14]) with u, restoring sorted order.
// Delete: parallel shift-select (depth 1). Insert: parallel merge (depth 2):
//   P[0]=min(w[0],u); P[j]=max(min(w[j],u), w[j-1]); P[14]=max(w[13],u).
// P[15] stays +INF.
__device__ __forceinline__ void replace_sorted(float P[16], float v, float u) {
    float w[14];
#pragma unroll
    for (int j = 0; j < 14; j++)
        w[j] = (P[j] < v) ? P[j] : P[j + 1];   // delete first occurrence of v
    P[0] = fminf(w[0], u);
#pragma unroll
    for (int j = 1; j < 14; j++)
        P[j] = fmaxf(fminf(w[j], u), w[j - 1]);
    P[14] = fmaxf(w[13], u);
}

__global__ __launch_bounds__(NTHREADS, 7)
void hpss_kernel(const float* __restrict__ S, float* __restrict__ out) {
    __shared__ float patch[PATCH_H][PITCH];
    __shared__ float harm[TILE_H][TILE_W + 1];

    const int bx  = blockIdx.x * TILE_W;
    const int by  = blockIdx.y * TILE_H;
    const int img = blockIdx.z;
    const float* __restrict__ Simg = S + (size_t)img * IMG_H * IMG_W;

    const int tid = threadIdx.x;

    // Cooperative patch load with zero padding.
#pragma unroll 4
    for (int idx = tid; idx < PATCH_H * PATCH_W; idx += NTHREADS) {
        int r = idx / PATCH_W;
        int c = idx - r * PATCH_W;
        int gh = by + r - HALO;
        int gw = bx + c - HALO;
        float val = 0.0f;
        if (gh >= 0 && gh < IMG_H && gw >= 0 && gw < IMG_W)
            val = Simg[gh * IMG_W + gw];
        patch[r][c] = val;
    }
    __syncthreads();

    // ---- Phase A: horizontal medians (harm); thread owns a 16-wide row run.
    {
        const int row = tid & 31;       // 0..31
        const int g   = tid >> 5;       // 0..3 -> cols g*16..g*16+15
        const int c0  = g * 16;
        const float* __restrict__ q = &patch[row + HALO][c0];

        float b[16], P[16];
#pragma unroll
        for (int j = 0; j < 16; j++) b[j] = q[15 + j];
        sort16(b);

#pragma unroll
        for (int j = 0; j < 15; j++) P[j] = q[j];   // L = positions 0..14
        P[15] = CUDART_INF_F;
        sort16(P);                                   // INF stays at P[15]

#pragma unroll
        for (int i = 0; i < 16; i++) {
            if (i > 0)
                replace_sorted(P, q[i - 1], q[31 + i - 1]); // drop L[i-1], add R[i-1]
            harm[row][c0 + i] = sel16th(P, b);
        }
    }
    __syncthreads();

    // ---- Phase B: vertical medians (perc); thread owns a 16-tall col run;
    //      combine with harm + S, write both output planes.
    {
        const int col = tid & 63;       // 0..63
        const int gy  = tid >> 6;       // 0..1 -> rows gy*16..gy*16+15
        const int r0  = gy * 16;
        const float* __restrict__ q = &patch[r0][col + HALO];

        float b[16], P[16];
#pragma unroll
        for (int j = 0; j < 16; j++) b[j] = q[(15 + j) * PITCH];
        sort16(b);

#pragma unroll
        for (int j = 0; j < 15; j++) P[j] = q[j * PITCH];
        P[15] = CUDART_INF_F;
        sort16(P);

        const size_t plane = (size_t)N_IMG * IMG_H * IMG_W;

#pragma unroll
        for (int i = 0; i < 16; i++) {
            if (i > 0)
                replace_sorted(P, q[(i - 1) * PITCH], q[(31 + i - 1) * PITCH]);
            float p = sel16th(P, b);

            int h_local = r0 + i;
            int gh = by + h_local;
            if (gh < IMG_H) {
                float hmed = harm[h_local][col];
                float s    = patch[h_local + HALO][col + HALO];

                float hh = hmed * hmed;
                float pp = p * p;
                float inv = 1.0f / (hh + pp);

                size_t o = (size_t)img * (IMG_H * IMG_W) + (size_t)gh * IMG_W
                         + (bx + col);
                out[o]         = s * (hh * inv);
                out[o + plane] = s * (pp * inv);
            }
        }
    }
}

extern "C" void kernel_launch(void* const* d_in, const int* in_sizes, int n_in,
                              void* d_out, int out_size) {
    const float* S = (const float*)d_in[0];
    float* out = (float*)d_out;
    (void)in_sizes; (void)n_in; (void)out_size;

    dim3 block(NTHREADS);
    dim3 grid(IMG_W / TILE_W, (IMG_H + TILE_H - 1) / TILE_H, N_IMG);
    hpss_kernel<<<grid, block>>>(S, out);
}

// round 14
// speedup vs baseline: 1.0005x; 1.0005x over previous
#include <cuda_runtime.h>
#include <math_constants.h>

// HPSS: S (2,2,1025,1024) fp32 -> (S*mask_h, S*mask_p); 31-tap medians along
// W (harm) and H (perc), zero padded; mask = med^2/(h^2+p^2).
//
// R14: R9 fp32 algorithm (bitonic-sorted shared base + incrementally
// maintained sorted private set + rank-15 two-array select), with alu->fma
// pipe rebalancing:
//   - sort compare-exchange: mn=FMNMX(alu); mx = (a+b)-mn  (2 fma ops)
//   - delete: float mask via set.lt.f32 (alu) + FADD/FFMA blend (2 fma)
// Insert and select remain on the alu pipe. Errors are O(ulp), far below
// the 1e-3 threshold.

#define IMG_H 1025
#define IMG_W 1024
#define N_IMG 4
#define HALO  15

#define TILE_W 64
#define TILE_H 32
#define PATCH_H (TILE_H + 2 * HALO)   // 62
#define PATCH_W (TILE_W + 2 * HALO)   // 94
#define PITCH   (PATCH_W + 1)         // 95 (odd -> conflict-free column access)
#define NTHREADS 128

// Compare-exchange with fma-pipe max: mn on alu pipe, s/mx on fma pipe.
__device__ __forceinline__ void ce_mix(float& a, float& b) {
    float mn = fminf(a, b);
    float s  = a + b;          // FADD  (fma pipe)
    float mx = s - mn;         // FADD  (fma pipe); exact to 1 ulp
    a = mn; b = mx;
}

// Bitonic sort, n=16: 80 CE, fully static register indexing.
__device__ __forceinline__ void sort16(float v[16]) {
#pragma unroll
    for (int k = 2; k <= 16; k <<= 1) {
#pragma unroll
        for (int j = k >> 1; j > 0; j >>= 1) {
#pragma unroll
            for (int i = 0; i < 16; i++) {
                int l = i ^ j;
                if (l > i) {
                    if ((i & k) == 0) ce_mix(v[i], v[l]);
                    else              ce_mix(v[l], v[i]);
                }
            }
        }
    }
}

// Rank-15 (16th smallest) of sorted P[0..14] u sorted b[0..15].
__device__ __forceinline__ float sel16th(const float P[16], const float b[16]) {
    float c[16];
    c[0] = b[15];
#pragma unroll
    for (int j = 1; j <= 15; j++) c[j] = fmaxf(P[j - 1], b[15 - j]);
#pragma unroll
    for (int s = 8; s >= 1; s >>= 1)
#pragma unroll
        for (int j = 0; j < s; j++) c[j] = fminf(c[j], c[j + s]);
    return c[0];
}

// Replace value v (present in sorted P[0..14]) with u.
// Delete: float mask (set.lt, alu) + FADD/FFMA blend (fma pipe).
// Insert: parallel depth-2 merge (alu pipe). P[15] stays +INF.
__device__ __forceinline__ void replace_sorted(float P[16], float v, float u) {
    float w[14];
#pragma unroll
    for (int j = 0; j < 14; j++) {
        float m;
        asm("set.lt.f32.f32 %0, %1, %2;" : "=f"(m) : "f"(P[j]), "f"(v));
        float d = P[j] - P[j + 1];                 // FADD (fma pipe)
        w[j] = __fmaf_rn(m, d, P[j + 1]);          // FFMA (fma pipe)
    }
    P[0] = fminf(w[0], u);
#pragma unroll
    for (int j = 1; j < 14; j++)
        P[j] = fmaxf(fminf(w[j], u), w[j - 1]);
    P[14] = fmaxf(w[13], u);
}

__global__ __launch_bounds__(NTHREADS)
void hpss_kernel(const float* __restrict__ S, float* __restrict__ out) {
    __shared__ float patch[PATCH_H][PITCH];
    __shared__ float harm[TILE_H][TILE_W + 1];

    const int bx  = blockIdx.x * TILE_W;
    const int by  = blockIdx.y * TILE_H;
    const int img = blockIdx.z;
    const float* __restrict__ Simg = S + (size_t)img * IMG_H * IMG_W;

    const int tid = threadIdx.x;

    // Cooperative patch load with zero padding.
#pragma unroll 4
    for (int idx = tid; idx < PATCH_H * PATCH_W; idx += NTHREADS) {
        int r = idx / PATCH_W;
        int c = idx - r * PATCH_W;
        int gh = by + r - HALO;
        int gw = bx + c - HALO;
        float val = 0.0f;
        if (gh >= 0 && gh < IMG_H && gw >= 0 && gw < IMG_W)
            val = Simg[gh * IMG_W + gw];
        patch[r][c] = val;
    }
    __syncthreads();

    // ---- Phase A: horizontal medians (harm); thread owns a 16-wide row run.
    {
        const int row = tid & 31;       // 0..31
        const int g   = tid >> 5;       // 0..3 -> cols g*16..g*16+15
        const int c0  = g * 16;
        const float* __restrict__ q = &patch[row + HALO][c0];

        float b[16], P[16];
#pragma unroll
        for (int j = 0; j < 16; j++) b[j] = q[15 + j];
        sort16(b);

#pragma unroll
        for (int j = 0; j < 15; j++) P[j] = q[j];   // L = positions 0..14
        P[15] = CUDART_INF_F;
        sort16(P);                                   // INF stays at P[15]

#pragma unroll
        for (int i = 0; i < 16; i++) {
            if (i > 0)
                replace_sorted(P, q[i - 1], q[31 + i - 1]); // drop L[i-1], add R[i-1]
            harm[row][c0 + i] = sel16th(P, b);
        }
    }
    __syncthreads();

    // ---- Phase B: vertical medians (perc); thread owns a 16-tall col run;
    //      combine with harm + S, write both output planes.
    {
        const int col = tid & 63;       // 0..63
        const int gy  = tid >> 6;       // 0..1 -> rows gy*16..gy*16+15
        const int r0  = gy * 16;
        const float* __restrict__ q = &patch[r0][col + HALO];

        float b[16], P[16];
#pragma unroll
        for (int j = 0; j < 16; j++) b[j] = q[(15 + j) * PITCH];
        sort16(b);

#pragma unroll
        for (int j = 0; j < 15; j++) P[j] = q[j * PITCH];
        P[15] = CUDART_INF_F;
        sort16(P);

        const size_t plane = (size_t)N_IMG * IMG_H * IMG_W;

#pragma unroll
        for (int i = 0; i < 16; i++) {
            if (i > 0)
                replace_sorted(P, q[(i - 1) * PITCH], q[(31 + i - 1) * PITCH]);
            float p = sel16th(P, b);

            int h_local = r0 + i;
            int gh = by + h_local;
            if (gh < IMG_H) {
                float hmed = harm[h_local][col];
                float s    = patch[h_local + HALO][col + HALO];

                float hh = hmed * hmed;
                float pp = p * p;
                float inv = 1.0f / (hh + pp);

                size_t o = (size_t)img * (IMG_H * IMG_W) + (size_t)gh * IMG_W
                         + (bx + col);
                out[o]         = s * (hh * inv);
                out[o + plane] = s * (pp * inv);
            }
        }
    }
}

extern "C" void kernel_launch(void* const* d_in, const int* in_sizes, int n_in,
                              void* d_out, int out_size) {
    const float* S = (const float*)d_in[0];
    float* out = (float*)d_out;
    (void)in_sizes; (void)n_in; (void)out_size;

    dim3 block(NTHREADS);
    dim3 grid(IMG_W / TILE_W, (IMG_H + TILE_H - 1) / TILE_H, N_IMG);
    hpss_kernel<<<grid, block>>>(S, out);
}

// round 15
// speedup vs baseline: 1.0920x; 1.0915x over previous
#include <cuda_runtime.h>
#include <math_constants.h>

// HPSS: S (2,2,1025,1024) fp32 -> (S*mask_h, S*mask_p); 31-tap medians along
// W (harm) and H (perc), zero padded; mask = med^2/(h^2+p^2).
//
// R15: R9 core (sorted shared base + incrementally maintained sorted private
// set + rank-15 two-array select, all fp32 FMNMX) with instruction-count cuts:
//   - optimal 60-CE sorting network (explicit static pairs) vs 80-CE bitonic
//   - interior-block fast path for the cooperative patch load (no per-element
//     bounds checks for ~80% of blocks)
//   - in-place delete(asc)/insert(desc) in replace_sorted (no temp array)

#define IMG_H 1025
#define IMG_W 1024
#define N_IMG 4
#define HALO  15

#define TILE_W 64
#define TILE_H 32
#define PATCH_H (TILE_H + 2 * HALO)   // 62
#define PATCH_W (TILE_W + 2 * HALO)   // 94
#define PITCH   (PATCH_W + 1)         // 95 (odd -> conflict-free column access)
#define NTHREADS 128

__device__ __forceinline__ void ce(float& a, float& b) {
    float mn = fminf(a, b);
    float mx = fmaxf(a, b);
    a = mn; b = mx;
}

// Optimal n=16 sorting network (Green), 60 compare-exchanges, all indices
// literal constants -> guaranteed register residency.
__device__ __forceinline__ void sort16(float v[16]) {
    ce(v[0],v[1]); ce(v[2],v[3]); ce(v[4],v[5]); ce(v[6],v[7]);
    ce(v[8],v[9]); ce(v[10],v[11]); ce(v[12],v[13]); ce(v[14],v[15]);
    ce(v[0],v[2]); ce(v[4],v[6]); ce(v[8],v[10]); ce(v[12],v[14]);
    ce(v[1],v[3]); ce(v[5],v[7]); ce(v[9],v[11]); ce(v[13],v[15]);
    ce(v[0],v[4]); ce(v[8],v[12]); ce(v[1],v[5]); ce(v[9],v[13]);
    ce(v[2],v[6]); ce(v[10],v[14]); ce(v[3],v[7]); ce(v[11],v[15]);
    ce(v[0],v[8]); ce(v[1],v[9]); ce(v[2],v[10]); ce(v[3],v[11]);
    ce(v[4],v[12]); ce(v[5],v[13]); ce(v[6],v[14]); ce(v[7],v[15]);
    ce(v[5],v[10]); ce(v[6],v[9]); ce(v[3],v[12]); ce(v[13],v[14]);
    ce(v[7],v[11]); ce(v[1],v[2]); ce(v[4],v[8]);
    ce(v[1],v[4]); ce(v[7],v[13]); ce(v[2],v[8]); ce(v[11],v[14]);
    ce(v[2],v[4]); ce(v[5],v[6]); ce(v[9],v[10]); ce(v[11],v[13]);
    ce(v[3],v[8]); ce(v[7],v[12]);
    ce(v[6],v[8]); ce(v[10],v[12]); ce(v[3],v[5]); ce(v[7],v[9]);
    ce(v[3],v[4]); ce(v[5],v[6]); ce(v[7],v[8]); ce(v[9],v[10]);
    ce(v[11],v[12]);
    ce(v[6],v[7]); ce(v[8],v[9]);
}

// Rank-15 (16th smallest) of sorted P[0..14] u sorted b[0..15].
__device__ __forceinline__ float sel16th(const float P[16], const float b[16]) {
    float c[16];
    c[0] = b[15];
#pragma unroll
    for (int j = 1; j <= 15; j++) c[j] = fmaxf(P[j - 1], b[15 - j]);
#pragma unroll
    for (int s = 8; s >= 1; s >>= 1)
#pragma unroll
        for (int j = 0; j < s; j++) c[j] = fminf(c[j], c[j + s]);
    return c[0];
}

// Replace value v (present in sorted P[0..14]) with u, in place.
// Delete ascending (slot j reads P[j+1] before it is rewritten next iter),
// then insert descending (slot j reads w[j]=P[j], w[j-1]=P[j-1], both still
// holding w-values when written top-down). P[15] stays +INF.
__device__ __forceinline__ void replace_sorted(float P[16], float v, float u) {
#pragma unroll
    for (int j = 0; j < 14; j++)
        P[j] = (P[j] < v) ? P[j] : P[j + 1];       // now P[0..13] = w[0..13]
    P[14] = fmaxf(P[13], u);
#pragma unroll
    for (int j = 13; j >= 1; j--)
        P[j] = fmaxf(fminf(P[j], u), P[j - 1]);
    P[0] = fminf(P[0], u);
}

__global__ __launch_bounds__(NTHREADS)
void hpss_kernel(const float* __restrict__ S, float* __restrict__ out) {
    __shared__ float patch[PATCH_H][PITCH];
    __shared__ float harm[TILE_H][TILE_W + 1];

    const int bx  = blockIdx.x * TILE_W;
    const int by  = blockIdx.y * TILE_H;
    const int img = blockIdx.z;
    const float* __restrict__ Simg = S + (size_t)img * IMG_H * IMG_W;

    const int tid = threadIdx.x;

    // Cooperative patch load. Interior blocks (halo fully inside the image)
    // take an unchecked fast path; edge blocks do per-element bounds checks.
    const bool interior = (blockIdx.x >= 1) & (blockIdx.x <= 14) &
                          (blockIdx.y >= 1) & (blockIdx.y <= 30);
    if (interior) {
        const float* __restrict__ base = Simg + (by - HALO) * IMG_W + (bx - HALO);
#pragma unroll 8
        for (int idx = tid; idx < PATCH_H * PATCH_W; idx += NTHREADS) {
            int r = idx / PATCH_W;
            int c = idx - r * PATCH_W;
            patch[r][c] = base[r * IMG_W + c];
        }
    } else {
#pragma unroll 4
        for (int idx = tid; idx < PATCH_H * PATCH_W; idx += NTHREADS) {
            int r = idx / PATCH_W;
            int c = idx - r * PATCH_W;
            int gh = by + r - HALO;
            int gw = bx + c - HALO;
            float val = 0.0f;
            if (gh >= 0 && gh < IMG_H && gw >= 0 && gw < IMG_W)
                val = Simg[gh * IMG_W + gw];
            patch[r][c] = val;
        }
    }
    __syncthreads();

    // ---- Phase A: horizontal medians (harm); thread owns a 16-wide row run.
    {
        const int row = tid & 31;       // 0..31
        const int g   = tid >> 5;       // 0..3 -> cols g*16..g*16+15
        const int c0  = g * 16;
        const float* __restrict__ q = &patch[row + HALO][c0];

        float b[16], P[16];
#pragma unroll
        for (int j = 0; j < 16; j++) b[j] = q[15 + j];
        sort16(b);

#pragma unroll
        for (int j = 0; j < 15; j++) P[j] = q[j];   // L = positions 0..14
        P[15] = CUDART_INF_F;
        sort16(P);                                   // INF stays at P[15]

#pragma unroll
        for (int i = 0; i < 16; i++) {
            if (i > 0)
                replace_sorted(P, q[i - 1], q[31 + i - 1]); // drop L[i-1], add R[i-1]
            harm[row][c0 + i] = sel16th(P, b);
        }
    }
    __syncthreads();

    // ---- Phase B: vertical medians (perc); thread owns a 16-tall col run;
    //      combine with harm + S, write both output planes.
    {
        const int col = tid & 63;       // 0..63
        const int gy  = tid >> 6;       // 0..1 -> rows gy*16..gy*16+15
        const int r0  = gy * 16;
        const float* __restrict__ q = &patch[r0][col + HALO];

        float b[16], P[16];
#pragma unroll
        for (int j = 0; j < 16; j++) b[j] = q[(15 + j) * PITCH];
        sort16(b);

#pragma unroll
        for (int j = 0; j < 15; j++) P[j] = q[j * PITCH];
        P[15] = CUDART_INF_F;
        sort16(P);

        const size_t plane = (size_t)N_IMG * IMG_H * IMG_W;

#pragma unroll
        for (int i = 0; i < 16; i++) {
            if (i > 0)
                replace_sorted(P, q[(i - 1) * PITCH], q[(31 + i - 1) * PITCH]);
            float p = sel16th(P, b);

            int h_local = r0 + i;
            int gh = by + h_local;
            if (gh < IMG_H) {
                float hmed = harm[h_local][col];
                float s    = patch[h_local + HALO][col + HALO];

                float hh = hmed * hmed;
                float pp = p * p;
                float inv = 1.0f / (hh + pp);

                size_t o = (size_t)img * (IMG_H * IMG_W) + (size_t)gh * IMG_W
                         + (bx + col);
                out[o]         = s * (hh * inv);
                out[o + plane] = s * (pp * inv);
            }
        }
    }
}

extern "C" void kernel_launch(void* const* d_in, const int* in_sizes, int n_in,
                              void* d_out, int out_size) {
    const float* S = (const float*)d_in[0];
    float* out = (float*)d_out;
    (void)in_sizes; (void)n_in; (void)out_size;

    dim3 block(NTHREADS);
    dim3 grid(IMG_W / TILE_W, (IMG_H + TILE_H - 1) / TILE_H, N_IMG);
    hpss_kernel<<<grid, block>>>(S, out);
}

// round 16
// speedup vs baseline: 1.1588x; 1.0612x over previous
#include <cuda_runtime.h>
#include <math_constants.h>

// HPSS: S (2,2,1025,1024) fp32 -> (S*mask_h, S*mask_p); 31-tap medians along
// W (harm) and H (perc), zero padded; mask = med^2/(h^2+p^2).
//
// R16: R15 core (60-CE Green sort network, sorted shared base + incremental
// sorted private set + rank-15 two-array select) with:
//   - warp-per-row cp.async patch loader for interior blocks (no per-element
//     integer division, no LDG->STS register dependency)
//   - row-structured predicated loader for edge blocks (no divisions)
//   - 56-CE sort for P (slot 15 = +INF -> its 4 comparators are no-ops)
//   - block-level hoist of the epilogue row-bounds check

#define IMG_H 1025
#define IMG_W 1024
#define N_IMG 4
#define HALO  15

#define TILE_W 64
#define TILE_H 32
#define PATCH_H (TILE_H + 2 * HALO)   // 62
#define PATCH_W (TILE_W + 2 * HALO)   // 94
#define PITCH   (PATCH_W + 1)         // 95 (odd -> conflict-free phase-A rows)
#define NTHREADS 128

__device__ __forceinline__ void ce(float& a, float& b) {
    float mn = fminf(a, b);
    float mx = fmaxf(a, b);
    a = mn; b = mx;
}

// Green's 16-input sorting network, 60 CE, all indices literal.
__device__ __forceinline__ void sort16(float v[16]) {
    ce(v[0],v[1]); ce(v[2],v[3]); ce(v[4],v[5]); ce(v[6],v[7]);
    ce(v[8],v[9]); ce(v[10],v[11]); ce(v[12],v[13]); ce(v[14],v[15]);
    ce(v[0],v[2]); ce(v[4],v[6]); ce(v[8],v[10]); ce(v[12],v[14]);
    ce(v[1],v[3]); ce(v[5],v[7]); ce(v[9],v[11]); ce(v[13],v[15]);
    ce(v[0],v[4]); ce(v[8],v[12]); ce(v[1],v[5]); ce(v[9],v[13]);
    ce(v[2],v[6]); ce(v[10],v[14]); ce(v[3],v[7]); ce(v[11],v[15]);
    ce(v[0],v[8]); ce(v[1],v[9]); ce(v[2],v[10]); ce(v[3],v[11]);
    ce(v[4],v[12]); ce(v[5],v[13]); ce(v[6],v[14]); ce(v[7],v[15]);
    ce(v[5],v[10]); ce(v[6],v[9]); ce(v[3],v[12]); ce(v[13],v[14]);
    ce(v[7],v[11]); ce(v[1],v[2]); ce(v[4],v[8]);
    ce(v[1],v[4]); ce(v[7],v[13]); ce(v[2],v[8]); ce(v[11],v[14]);
    ce(v[2],v[4]); ce(v[5],v[6]); ce(v[9],v[10]); ce(v[11],v[13]);
    ce(v[3],v[8]); ce(v[7],v[12]);
    ce(v[6],v[8]); ce(v[10],v[12]); ce(v[3],v[5]); ce(v[7],v[9]);
    ce(v[3],v[4]); ce(v[5],v[6]); ce(v[7],v[8]); ce(v[9],v[10]);
    ce(v[11],v[12]);
    ce(v[6],v[7]); ce(v[8],v[9]);
}

// Same network with all comparators touching slot 15 removed (56 CE).
// Precondition: v[15] == +INF (those comparators are provable no-ops).
__device__ __forceinline__ void sort15p(float v[16]) {
    ce(v[0],v[1]); ce(v[2],v[3]); ce(v[4],v[5]); ce(v[6],v[7]);
    ce(v[8],v[9]); ce(v[10],v[11]); ce(v[12],v[13]);
    ce(v[0],v[2]); ce(v[4],v[6]); ce(v[8],v[10]); ce(v[12],v[14]);
    ce(v[1],v[3]); ce(v[5],v[7]); ce(v[9],v[11]);
    ce(v[0],v[4]); ce(v[8],v[12]); ce(v[1],v[5]); ce(v[9],v[13]);
    ce(v[2],v[6]); ce(v[10],v[14]); ce(v[3],v[7]);
    ce(v[0],v[8]); ce(v[1],v[9]); ce(v[2],v[10]); ce(v[3],v[11]);
    ce(v[4],v[12]); ce(v[5],v[13]); ce(v[6],v[14]);
    ce(v[5],v[10]); ce(v[6],v[9]); ce(v[3],v[12]); ce(v[13],v[14]);
    ce(v[7],v[11]); ce(v[1],v[2]); ce(v[4],v[8]);
    ce(v[1],v[4]); ce(v[7],v[13]); ce(v[2],v[8]); ce(v[11],v[14]);
    ce(v[2],v[4]); ce(v[5],v[6]); ce(v[9],v[10]); ce(v[11],v[13]);
    ce(v[3],v[8]); ce(v[7],v[12]);
    ce(v[6],v[8]); ce(v[10],v[12]); ce(v[3],v[5]); ce(v[7],v[9]);
    ce(v[3],v[4]); ce(v[5],v[6]); ce(v[7],v[8]); ce(v[9],v[10]);
    ce(v[11],v[12]);
    ce(v[6],v[7]); ce(v[8],v[9]);
}

// Rank-15 (16th smallest) of sorted P[0..14] u sorted b[0..15].
__device__ __forceinline__ float sel16th(const float P[16], const float b[16]) {
    float c[16];
    c[0] = b[15];
#pragma unroll
    for (int j = 1; j <= 15; j++) c[j] = fmaxf(P[j - 1], b[15 - j]);
#pragma unroll
    for (int s = 8; s >= 1; s >>= 1)
#pragma unroll
        for (int j = 0; j < s; j++) c[j] = fminf(c[j], c[j + s]);
    return c[0];
}

// Replace value v (present in sorted P[0..14]) with u, in place.
// Delete ascending, insert descending (aliasing-safe). P[15] stays +INF.
__device__ __forceinline__ void replace_sorted(float P[16], float v, float u) {
#pragma unroll
    for (int j = 0; j < 14; j++)
        P[j] = (P[j] < v) ? P[j] : P[j + 1];
    P[14] = fmaxf(P[13], u);
#pragma unroll
    for (int j = 13; j >= 1; j--)
        P[j] = fmaxf(fminf(P[j], u), P[j - 1]);
    P[0] = fminf(P[0], u);
}

__global__ __launch_bounds__(NTHREADS)
void hpss_kernel(const float* __restrict__ S, float* __restrict__ out) {
    __shared__ float patch[PATCH_H][PITCH];
    __shared__ float harm[TILE_H][TILE_W + 1];

    const int bx  = blockIdx.x * TILE_W;
    const int by  = blockIdx.y * TILE_H;
    const int img = blockIdx.z;
    const float* __restrict__ Simg = S + (size_t)img * IMG_H * IMG_W;

    const int tid  = threadIdx.x;
    const int wrp  = tid >> 5;
    const int lane = tid & 31;

    // ---- Patch load: warp-per-row, no divisions.
    const bool interior = (blockIdx.x >= 1) & (blockIdx.x <= 14) &
                          (blockIdx.y >= 1) & (blockIdx.y <= 30);
    if (interior) {
        // cp.async: gmem -> smem, no register round-trip, fire-and-forget.
        const float* __restrict__ base = Simg + (by - HALO) * IMG_W + (bx - HALO);
        unsigned sbase = (unsigned)__cvta_generic_to_shared(&patch[0][0]);
        for (int r = wrp; r < PATCH_H; r += 4) {
            const float* src = base + r * IMG_W + lane;
            unsigned dst = sbase + (unsigned)(r * PITCH + lane) * 4u;
            asm volatile("cp.async.ca.shared.global [%0], [%1], 4;" ::
                         "r"(dst), "l"(src));
            asm volatile("cp.async.ca.shared.global [%0], [%1], 4;" ::
                         "r"(dst + 128u), "l"(src + 32));
            if (lane < PITCH - 64)
                asm volatile("cp.async.ca.shared.global [%0], [%1], 4;" ::
                             "r"(dst + 256u), "l"(src + 64));
        }
        asm volatile("cp.async.commit_group;");
        asm volatile("cp.async.wait_group 0;");
    } else {
        // Edge blocks: row-structured predicated loads (no divisions).
        for (int r = wrp; r < PATCH_H; r += 4) {
            int gh = by + r - HALO;
            bool row_ok = (gh >= 0) & (gh < IMG_H);
            const float* rowp = Simg + gh * IMG_W + (bx - HALO);
#pragma unroll
            for (int k = 0; k < 3; k++) {
                int c = lane + k * 32;
                if (c < PITCH) {
                    int gw = bx + c - HALO;
                    bool ok = row_ok & (gw >= 0) & (gw < IMG_W);
                    patch[r][c] = ok ? rowp[c] : 0.0f;
                }
            }
        }
    }
    __syncthreads();

    // ---- Phase A: horizontal medians (harm); thread owns a 16-wide row run.
    {
        const int row = tid & 31;       // 0..31
        const int g   = tid >> 5;       // 0..3 -> cols g*16..g*16+15
        const int c0  = g * 16;
        const float* __restrict__ q = &patch[row + HALO][c0];

        float b[16], P[16];
#pragma unroll
        for (int j = 0; j < 16; j++) b[j] = q[15 + j];
        sort16(b);

#pragma unroll
        for (int j = 0; j < 15; j++) P[j] = q[j];   // L = positions 0..14
        P[15] = CUDART_INF_F;
        sort15p(P);                                  // INF stays at P[15]

#pragma unroll
        for (int i = 0; i < 16; i++) {
            if (i > 0)
                replace_sorted(P, q[i - 1], q[31 + i - 1]);
            harm[row][c0 + i] = sel16th(P, b);
        }
    }
    __syncthreads();

    // ---- Phase B: vertical medians (perc); combine + write both planes.
    {
        const int col = tid & 63;       // 0..63
        const int gy  = tid >> 6;       // 0..1 -> rows gy*16..gy*16+15
        const int r0  = gy * 16;
        const float* __restrict__ q = &patch[r0][col + HALO];

        float b[16], P[16];
#pragma unroll
        for (int j = 0; j < 16; j++) b[j] = q[(15 + j) * PITCH];
        sort16(b);

#pragma unroll
        for (int j = 0; j < 15; j++) P[j] = q[j * PITCH];
        P[15] = CUDART_INF_F;
        sort15p(P);

        const size_t plane = (size_t)N_IMG * IMG_H * IMG_W;
        const bool rows_full = (by + TILE_H <= IMG_H);

        if (rows_full) {
#pragma unroll
            for (int i = 0; i < 16; i++) {
                if (i > 0)
                    replace_sorted(P, q[(i - 1) * PITCH], q[(31 + i - 1) * PITCH]);
                float p = sel16th(P, b);

                int h_local = r0 + i;
                float hmed = harm[h_local][col];
                float s    = patch[h_local + HALO][col + HALO];

                float hh = hmed * hmed;
                float pp = p * p;
                float inv = 1.0f / (hh + pp);

                size_t o = (size_t)img * (IMG_H * IMG_W)
                         + (size_t)(by + h_local) * IMG_W + (bx + col);
                out[o]         = s * (hh * inv);
                out[o + plane] = s * (pp * inv);
            }
        } else {
#pragma unroll
            for (int i = 0; i < 16; i++) {
                if (i > 0)
                    replace_sorted(P, q[(i - 1) * PITCH], q[(31 + i - 1) * PITCH]);
                float p = sel16th(P, b);

                int h_local = r0 + i;
                int gh = by + h_local;
                if (gh < IMG_H) {
                    float hmed = harm[h_local][col];
                    float s    = patch[h_local + HALO][col + HALO];

                    float hh = hmed * hmed;
                    float pp = p * p;
                    float inv = 1.0f / (hh + pp);

                    size_t o = (size_t)img * (IMG_H * IMG_W)
                             + (size_t)gh * IMG_W + (bx + col);
                    out[o]         = s * (hh * inv);
                    out[o + plane] = s * (pp * inv);
                }
            }
        }
    }
}

extern "C" void kernel_launch(void* const* d_in, const int* in_sizes, int n_in,
                              void* d_out, int out_size) {
    const float* S = (const float*)d_in[0];
    float* out = (float*)d_out;
    (void)in_sizes; (void)n_in; (void)out_size;

    dim3 block(NTHREADS);
    dim3 grid(IMG_W / TILE_W, (IMG_H + TILE_H - 1) / TILE_H, N_IMG);
    hpss_kernel<<<grid, block>>>(S, out);
}